// round 14
// baseline (speedup 1.0000x reference)
#include <cuda_runtime.h>
#include <cstdint>

// x: [8, 64, 64, 64, 64] fp32. Per (b,c) slice of 64^3:
//   s = sum over 2x2x2 windows of (max(window) + mean(window))
//   pooled[b,c] = s^2 ;  out[b,c] = pooled / max(||pooled[b,:]||_2, 1e-12)
//
// TMA-path experiment: 2048 blocks x 128 thr, each block streams its 256 KB
// quarter-slice via cp.async.bulk (UBLKCP) into 2 x 16 KB smem buffers,
// bypassing the L1tex/LSU wavefront path entirely. 16 stages/block; each
// stage = two 8 KB bulk copies (w-halves of an h-plane pair), expect_tx=16KB.
// Tests whether the 80% DRAM plateau is request-path or DRAM-side.

#define CH 4
#define NBC 512
#define NBLK (NBC * CH)        // 2048
#define STAGE_FLOATS 4096      // 16 KB
#define NSTAGE 16

__device__ float g_partial[NBLK];
__device__ unsigned int g_counter = 0;

__device__ __forceinline__ uint32_t smem_u32(const void* p) {
    uint32_t a;
    asm("{ .reg .u64 t; cvta.to.shared.u64 t, %1; cvt.u32.u64 %0, t; }"
        : "=r"(a) : "l"(p));
    return a;
}

__device__ __forceinline__ void mbar_init(uint32_t mbar, uint32_t cnt) {
    asm volatile("mbarrier.init.shared.b64 [%0], %1;" :: "r"(mbar), "r"(cnt) : "memory");
}
__device__ __forceinline__ void mbar_expect_tx(uint32_t mbar, uint32_t bytes) {
    asm volatile("mbarrier.arrive.expect_tx.shared.b64 _, [%0], %1;"
                 :: "r"(mbar), "r"(bytes) : "memory");
}
__device__ __forceinline__ void bulk_g2s(uint32_t dst, const void* src,
                                         uint32_t bytes, uint32_t mbar) {
    asm volatile("cp.async.bulk.shared::cta.global.mbarrier::complete_tx::bytes "
                 "[%0], [%1], %2, [%3];"
                 :: "r"(dst), "l"(src), "r"(bytes), "r"(mbar) : "memory");
}
__device__ __forceinline__ void mbar_wait(uint32_t mbar, uint32_t parity) {
    uint32_t done;
    asm volatile("{\n\t.reg .pred p;\n\t"
                 "mbarrier.try_wait.parity.acquire.cta.shared::cta.b64 p, [%1], %2;\n\t"
                 "selp.b32 %0, 1, 0, p;\n\t}"
                 : "=r"(done) : "r"(mbar), "r"(parity) : "memory");
    while (!done) {
        asm volatile("{\n\t.reg .pred p;\n\t"
                     "mbarrier.try_wait.parity.acquire.cta.shared::cta.b64 p, [%1], %2, 0x989680;\n\t"
                     "selp.b32 %0, 1, 0, p;\n\t}"
                     : "=r"(done) : "r"(mbar), "r"(parity) : "memory");
    }
}

__global__ __launch_bounds__(128) void fused_pool_kernel(const float* __restrict__ x,
                                                         float* __restrict__ out) {
    extern __shared__ float buf[];               // 2 * 4096 floats (32 KB)
    __shared__ alignas(8) unsigned long long mbar_store[2];
    __shared__ float swarp[4];
    __shared__ int s_islast;

    const int bc = blockIdx.x >> 2;
    const int q  = blockIdx.x & 3;               // quarter: h2 in [q*8, q*8+8)
    const int tid = threadIdx.x;                 // 128 threads
    const int tx  = tid & 15;                    // d-quad
    const int g   = tid >> 4;                    // 0..7: w2 base within half

    const float* base = x + (size_t)bc * (64 * 64 * 64) + (size_t)(q * 16) * 4096;
    const uint32_t mb0 = smem_u32(&mbar_store[0]);
    const uint32_t buf_s = smem_u32(buf);

    if (tid == 0) { mbar_init(mb0, 1); mbar_init(mb0 + 8, 1); }
    __syncthreads();

    // stage s: h2-pair hp = s>>1, w-half wh = s&1.
    //   copy0: plane 2*hp,   rows [wh*32, wh*32+32)  (8 KB) -> buf half + 0
    //   copy1: plane 2*hp+1, same rows               (8 KB) -> buf half + 2048
    // src offsets (floats): (2*hp + p)*4096 + wh*2048
    if (tid == 0) {
        #pragma unroll
        for (int s = 0; s < 2; s++) {
            const int hp = s >> 1, wh = s & 1;
            const uint32_t mb = mb0 + (uint32_t)(s & 1) * 8;
            const uint32_t dst = buf_s + (uint32_t)(s & 1) * (STAGE_FLOATS * 4);
            mbar_expect_tx(mb, STAGE_FLOATS * 4);
            bulk_g2s(dst,        base + (2 * hp)     * 4096 + wh * 2048, 8192, mb);
            bulk_g2s(dst + 8192, base + (2 * hp + 1) * 4096 + wh * 2048, 8192, mb);
        }
    }

    float acc = 0.0f;

    for (int s = 0; s < NSTAGE; s++) {
        const int bsel = s & 1;
        mbar_wait(mb0 + (uint32_t)bsel * 8, (uint32_t)((s >> 1) & 1));

        // compute this 16 KB: rows lw = 0..31 of both planes; w2l in [0,16)
        const float* pb = buf + bsel * STAGE_FLOATS;
        #pragma unroll
        for (int w2i = 0; w2i < 2; w2i++) {      // w2l = g, g+8
            const int w2l = g + 8 * w2i;
            const float* r = pb + (2 * w2l) * 64 + (tx << 2);
            const float4 a = *(const float4*)(r);              // plane0 row 2w2l
            const float4 b = *(const float4*)(r + 64);         // plane0 row 2w2l+1
            const float4 c = *(const float4*)(r + 2048);       // plane1 row 2w2l
            const float4 d = *(const float4*)(r + 2048 + 64);  // plane1 row 2w2l+1

            float m0 = fmaxf(fmaxf(fmaxf(a.x, a.y), fmaxf(b.x, b.y)),
                             fmaxf(fmaxf(c.x, c.y), fmaxf(d.x, d.y)));
            float m1 = fmaxf(fmaxf(fmaxf(a.z, a.w), fmaxf(b.z, b.w)),
                             fmaxf(fmaxf(c.z, c.w), fmaxf(d.z, d.w)));
            float sum = (a.x + a.y + a.z + a.w) + (b.x + b.y + b.z + b.w)
                      + (c.x + c.y + c.z + c.w) + (d.x + d.y + d.z + d.w);
            acc += m0 + m1 + sum * 0.125f;
        }

        __syncthreads();                         // all reads done before overwrite
        const int sn = s + 2;
        if (tid == 0 && sn < NSTAGE) {
            const int hp = sn >> 1, wh = sn & 1;
            const uint32_t mb = mb0 + (uint32_t)bsel * 8;
            const uint32_t dst = buf_s + (uint32_t)bsel * (STAGE_FLOATS * 4);
            mbar_expect_tx(mb, STAGE_FLOATS * 4);
            bulk_g2s(dst,        base + (2 * hp)     * 4096 + wh * 2048, 8192, mb);
            bulk_g2s(dst + 8192, base + (2 * hp + 1) * 4096 + wh * 2048, 8192, mb);
        }
    }

    // block reduce: warp shuffle then smem across 4 warps
    #pragma unroll
    for (int off = 16; off > 0; off >>= 1)
        acc += __shfl_xor_sync(0xFFFFFFFFu, acc, off);
    if ((tid & 31) == 0) swarp[tid >> 5] = acc;
    __syncthreads();

    if (tid == 0) {
        g_partial[blockIdx.x] = swarp[0] + swarp[1] + swarp[2] + swarp[3];
        __threadfence();                         // publish before ticket
        unsigned int old = atomicAdd(&g_counter, 1u);
        s_islast = (old == (unsigned int)(gridDim.x - 1));
    }
    __syncthreads();
    if (!s_islast) return;

    // ---- last block: finalize (all 2048 partials visible) ----
    __threadfence();
    __shared__ float s_norm[8];

    const int b  = tid >> 4;                     // 0..7
    const int c4 = (tid & 15) << 2;              // 0,4,...,60

    float p[4], qsum = 0.0f;
    #pragma unroll
    for (int k = 0; k < 4; k++) {
        const int idx = ((b << 6) + c4 + k) * CH;
        const float s = g_partial[idx] + g_partial[idx + 1]
                      + g_partial[idx + 2] + g_partial[idx + 3];
        p[k] = s * s;
        qsum += p[k] * p[k];
    }
    #pragma unroll
    for (int off = 8; off > 0; off >>= 1)
        qsum += __shfl_xor_sync(0xFFFFFFFFu, qsum, off);

    if ((tid & 15) == 0) s_norm[b] = fmaxf(sqrtf(qsum), 1e-12f);
    __syncthreads();

    const float inv = 1.0f / s_norm[b];
    #pragma unroll
    for (int k = 0; k < 4; k++)
        out[(b << 6) + c4 + k] = p[k] * inv;

    if (tid == 0) g_counter = 0;                 // reset for next graph replay
}

extern "C" void kernel_launch(void* const* d_in, const int* in_sizes, int n_in,
                              void* d_out, int out_size) {
    const float* x = (const float*)d_in[0];
    float* out = (float*)d_out;
    fused_pool_kernel<<<NBLK, 128, 2 * STAGE_FLOATS * sizeof(float)>>>(x, out);
}

// round 17
// speedup vs baseline: 1.0035x; 1.0035x over previous
#include <cuda_runtime.h>

// x: [8, 64, 64, 64, 64] fp32. Per (b,c) slice of 64^3:
//   s = sum over 2x2x2 windows of (max(window) + mean(window))
//   pooled[b,c] = s^2 ;  out[b,c] = pooled / max(||pooled[b,:]||_2, 1e-12)
//
// FINAL (converged after 14-round sweep): 2048 blocks x 128 threads =
// 512 slices x 4 quarter-slices (256 KB each). 32 regs -> all 2048 blocks
// resident in one wave. Plain LDG.128, fully coalesced, 4 batched loads per
// iter. Fused last-block finalize (atomic ticket).
//
// Convergence evidence: DRAM% pinned at 79-81.5% across occupancy 38-85%,
// block sizes 64-256, static/balanced/work-stealing scheduling, AND the TMA
// bulk-copy path (R14: 81.3% at occ=38%) -> the ~6.4 TB/s plateau is the
// chip's DRAM-side streaming ceiling, path-independent. 512 MiB mandatory
// read / 6.4 TB/s ~= 80 us = this kernel.

#define CH 4
#define NBC 512
#define NBLK (NBC * CH)   // 2048

__device__ float g_partial[NBLK];
__device__ unsigned int g_counter = 0;

__global__ __launch_bounds__(128, 16) void fused_pool_kernel(const float* __restrict__ x,
                                                             float* __restrict__ out) {
    const int bc = blockIdx.x >> 2;
    const int q  = blockIdx.x & 3;     // quarter: h2 in [q*8, q*8+8)

    const int tid = threadIdx.x;       // 128 threads
    const int tx  = tid & 15;          // d-group: d = 4*tx..4*tx+3 (two d2 windows)
    const int g   = tid >> 4;          // 0..7: w2 start; strides w2 by 8

    // start: h2 = q*8, w2 = g, d = 4*tx
    const float* r0 = x + (size_t)bc * (64 * 64 * 64)
                        + ((size_t)(q * 16) * 4096) + (2 * g * 64) + (tx << 2);

    float acc = 0.0f;

    for (int h2i = 0; h2i < 8; h2i++) {           // 8 h2 rows in this quarter
        const float* r = r0;
        #pragma unroll
        for (int w2i = 0; w2i < 4; w2i++) {       // w2 = g, g+8, g+16, g+24
            const float4 a = *(const float4*)(r);                 // (2h2,   2w2  )
            const float4 b = *(const float4*)(r + 64);            // (2h2,   2w2+1)
            const float4 c = *(const float4*)(r + 4096);          // (2h2+1, 2w2  )
            const float4 d = *(const float4*)(r + 4096 + 64);     // (2h2+1, 2w2+1)

            float m0 = fmaxf(fmaxf(fmaxf(a.x, a.y), fmaxf(b.x, b.y)),
                             fmaxf(fmaxf(c.x, c.y), fmaxf(d.x, d.y)));
            float m1 = fmaxf(fmaxf(fmaxf(a.z, a.w), fmaxf(b.z, b.w)),
                             fmaxf(fmaxf(c.z, c.w), fmaxf(d.z, d.w)));

            float sum = (a.x + a.y + a.z + a.w) + (b.x + b.y + b.z + b.w)
                      + (c.x + c.y + c.z + c.w) + (d.x + d.y + d.z + d.w);

            acc += m0 + m1 + sum * 0.125f;
            r += 2 * 8 * 64;                      // w2 += 8
        }
        r0 += 2 * 4096;                           // h2 += 1
    }

    // block reduce: warp shuffle then smem across 4 warps
    __shared__ float swarp[4];
    __shared__ int s_islast;
    #pragma unroll
    for (int off = 16; off > 0; off >>= 1)
        acc += __shfl_xor_sync(0xFFFFFFFFu, acc, off);
    if ((tid & 31) == 0) swarp[tid >> 5] = acc;
    __syncthreads();

    if (tid == 0) {
        float t = swarp[0] + swarp[1] + swarp[2] + swarp[3];
        g_partial[blockIdx.x] = t;
        __threadfence();                          // publish before ticket
        unsigned int old = atomicAdd(&g_counter, 1u);
        s_islast = (old == (unsigned int)(gridDim.x - 1));
    }
    __syncthreads();
    if (!s_islast) return;

    // ---- last block: finalize (all 2048 partials visible) ----
    __threadfence();
    __shared__ float s_norm[8];

    // thread t -> batch b = t>>4, channels c4 = (t&15)*4 .. +3
    const int b  = tid >> 4;           // 0..7
    const int c4 = (tid & 15) << 2;    // 0,4,...,60

    float p[4], qsum = 0.0f;
    #pragma unroll
    for (int k = 0; k < 4; k++) {
        const int idx = ((b << 6) + c4 + k) * CH;
        const float s = g_partial[idx] + g_partial[idx + 1]
                      + g_partial[idx + 2] + g_partial[idx + 3];
        p[k] = s * s;
        qsum += p[k] * p[k];
    }

    // reduce qsum over the 16 threads of the same batch (contiguous lanes)
    #pragma unroll
    for (int off = 8; off > 0; off >>= 1)
        qsum += __shfl_xor_sync(0xFFFFFFFFu, qsum, off);

    if ((tid & 15) == 0) s_norm[b] = fmaxf(sqrtf(qsum), 1e-12f);
    __syncthreads();

    const float inv = 1.0f / s_norm[b];
    #pragma unroll
    for (int k = 0; k < 4; k++)
        out[(b << 6) + c4 + k] = p[k] * inv;

    if (tid == 0) g_counter = 0;       // reset for next graph replay
}

extern "C" void kernel_launch(void* const* d_in, const int* in_sizes, int n_in,
                              void* d_out, int out_size) {
    const float* x = (const float*)d_in[0];
    float* out = (float*)d_out;
    fused_pool_kernel<<<NBLK, 128>>>(x, out);
}